// round 1
// baseline (speedup 1.0000x reference)
#include <cuda_runtime.h>
#include <cstdint>

#define BSZ   256
#define SEQ   1024
#define HID   512
#define TGT   256
#define NCTA  128
#define TPB   128
#define NPAIR 128   // 256 batch rows packed as 128 float2 pairs

// Double-buffered hidden state: [buf][k * NPAIR + pair], pair p holds rows (2p, 2p+1)
__device__ float2 g_h[2][HID * NPAIR];
__device__ unsigned g_bar;

__global__ void k_init() { g_bar = 0u; }

// Packed dual-FMA: d = a*b + c on both f32 lanes (B300 FFMA2 — full-rate fp32)
__device__ __forceinline__ void ffma2(float2& d, float2 a, float2 b, float2 c) {
    asm("{\n\t"
        ".reg .b64 ra, rb, rc, rd;\n\t"
        "mov.b64 ra, {%2, %3};\n\t"
        "mov.b64 rb, {%4, %5};\n\t"
        "mov.b64 rc, {%6, %7};\n\t"
        "fma.rn.f32x2 rd, ra, rb, rc;\n\t"
        "mov.b64 {%0, %1}, rd;\n\t"
        "}"
        : "=f"(d.x), "=f"(d.y)
        : "f"(a.x), "f"(a.y), "f"(b.x), "f"(b.y), "f"(c.x), "f"(c.y));
}

__device__ __forceinline__ float sigf(float x) {
    return __fdividef(1.0f, 1.0f + __expf(-x));
}
__device__ __forceinline__ float tanh_(float x) {
    return __fdividef(2.0f, 1.0f + __expf(-2.0f * x)) - 1.0f;
}

// Monotonic-counter grid barrier (all NCTA CTAs co-resident: 1 CTA/SM, 128 <= 148)
__device__ __forceinline__ void grid_barrier(unsigned target) {
    __syncthreads();
    if (threadIdx.x == 0) {
        __threadfence();                 // release: h stores visible before arrive
        atomicAdd(&g_bar, 1u);
        unsigned v;
        do {
            asm volatile("ld.acquire.gpu.u32 %0, [%1];" : "=r"(v) : "l"(&g_bar));
        } while (v < target);
    }
    __syncthreads();
}

// 4 k-steps of the gate GEMM: acc[g] += h_k * w[g][k]  (w pre-splatted {w,w})
template <bool XDOT>
__device__ __forceinline__ void compute4(const float2* h4,
                                         const float2* __restrict__ ws,
                                         const float2* __restrict__ ls,
                                         int k0, float2* acc, float2& xd) {
    if (XDOT) {
        const float4* l4 = reinterpret_cast<const float4*>(ls + k0);
        float4 la = l4[0];
        float4 lb = l4[1];
        ffma2(xd, h4[0], make_float2(la.x, la.y), xd);
        ffma2(xd, h4[1], make_float2(la.z, la.w), xd);
        ffma2(xd, h4[2], make_float2(lb.x, lb.y), xd);
        ffma2(xd, h4[3], make_float2(lb.z, lb.w), xd);
    }
#pragma unroll
    for (int g = 0; g < 16; g++) {
        const float4* w4 = reinterpret_cast<const float4*>(ws + g * HID + k0);
        float4 wa = w4[0];
        float4 wb = w4[1];
        ffma2(acc[g], h4[0], make_float2(wa.x, wa.y), acc[g]);
        ffma2(acc[g], h4[1], make_float2(wa.z, wa.w), acc[g]);
        ffma2(acc[g], h4[2], make_float2(wb.x, wb.y), acc[g]);
        ffma2(acc[g], h4[3], make_float2(wb.z, wb.w), acc[g]);
    }
}

// Full K=512 reduction with double-buffered L2 (__ldcg) prefetch of h
template <bool XDOT>
__device__ __forceinline__ void kloop(const float2* __restrict__ hin,
                                      const float2* __restrict__ ws,
                                      const float2* __restrict__ ls,
                                      int tid, float2* acc, float2& xd) {
    float2 bufA[4], bufB[4];
#pragma unroll
    for (int u = 0; u < 4; u++) bufA[u] = __ldcg(hin + (u) * NPAIR + tid);
#pragma unroll
    for (int u = 0; u < 4; u++) bufB[u] = __ldcg(hin + (4 + u) * NPAIR + tid);

#pragma unroll 1
    for (int k0 = 0; k0 < HID; k0 += 8) {
        float2 h4[4];
#pragma unroll
        for (int u = 0; u < 4; u++) h4[u] = bufA[u];
        if (k0 + 8 < HID) {
#pragma unroll
            for (int u = 0; u < 4; u++) bufA[u] = __ldcg(hin + (k0 + 8 + u) * NPAIR + tid);
        }
        compute4<XDOT>(h4, ws, ls, k0, acc, xd);

#pragma unroll
        for (int u = 0; u < 4; u++) h4[u] = bufB[u];
        if (k0 + 8 < HID) {
#pragma unroll
            for (int u = 0; u < 4; u++) bufB[u] = __ldcg(hin + (k0 + 12 + u) * NPAIR + tid);
        }
        compute4<XDOT>(h4, ws, ls, k0 + 4, acc, xd);
    }
}

extern __shared__ float2 dynsmem[];

__global__ void __launch_bounds__(TPB, 1)
seq2seq_kernel(const float* __restrict__ inp,
               const float* __restrict__ eWih, const float* __restrict__ eWhh,
               const float* __restrict__ ebih, const float* __restrict__ ebhh,
               const float* __restrict__ dWih, const float* __restrict__ dWhh,
               const float* __restrict__ dbih, const float* __restrict__ dbhh,
               const float* __restrict__ linW, const float* __restrict__ linb,
               float* __restrict__ out) {
    float2* wsE = dynsmem;              // [16][HID] splatted enc Whh slice
    float2* wsD = wsE + 16 * HID;       // [16][HID] splatted dec Whh slice
    float2* ls  = wsD + 16 * HID;       // [HID]     splatted lin_W
    __shared__ float bsE[16], wxE[16], bsD[16], wxD[16];
    __shared__ float s_linb;

    const int tid = threadIdx.x;
    const int cta = blockIdx.x;
    const int c0  = cta * 4;            // this CTA's first hidden column

    // Stage weights: gate column j = gate*HID + (c0+ci), g = gate*4 + ci
    for (int idx = tid; idx < 16 * HID; idx += TPB) {
        int g = idx >> 9;
        int k = idx & (HID - 1);
        int gate = g >> 2, ci = g & 3;
        int j = gate * HID + c0 + ci;
        float we = eWhh[j * HID + k];
        float wd = dWhh[j * HID + k];
        wsE[idx] = make_float2(we, we);
        wsD[idx] = make_float2(wd, wd);
    }
    for (int k = tid; k < HID; k += TPB) {
        float lw = linW[k];
        ls[k] = make_float2(lw, lw);
    }
    if (tid < 16) {
        int gate = tid >> 2, ci = tid & 3;
        int j = gate * HID + c0 + ci;
        bsE[tid] = ebih[j] + ebhh[j];
        wxE[tid] = eWih[j];
        bsD[tid] = dbih[j] + dbhh[j];
        wxD[tid] = dWih[j];
    }
    if (tid == 0) s_linb = linb[0];

    // Zero initial hidden state (own columns of buffer 0)
#pragma unroll
    for (int ci = 0; ci < 4; ci++)
        g_h[0][(c0 + ci) * NPAIR + tid] = make_float2(0.f, 0.f);

    float2 c2[4];
#pragma unroll
    for (int ci = 0; ci < 4; ci++) c2[ci] = make_float2(0.f, 0.f);

    unsigned bt = 0;
    const int b0 = 2 * tid, b1 = 2 * tid + 1;

    // ---------------- encoder: 1024 steps ----------------
    for (int s = 0; s < SEQ; s++) {
        bt += NCTA;
        grid_barrier(bt);

        float2 x2;
        x2.x = __ldg(inp + b0 * SEQ + s);
        x2.y = __ldg(inp + b1 * SEQ + s);

        float2 acc[16];
#pragma unroll
        for (int g = 0; g < 16; g++) {
            float b = bsE[g], w = wxE[g];
            acc[g].x = fmaf(x2.x, w, b);
            acc[g].y = fmaf(x2.y, w, b);
        }
        float2 xd = make_float2(0.f, 0.f);
        kloop<false>(g_h[s & 1], wsE, ls, tid, acc, xd);

        float2* hout = g_h[(s + 1) & 1];
#pragma unroll
        for (int ci = 0; ci < 4; ci++) {
            float2 gi = acc[ci], gf = acc[4 + ci], gg = acc[8 + ci], go = acc[12 + ci];
            float cnx = sigf(gf.x) * c2[ci].x + sigf(gi.x) * tanh_(gg.x);
            float cny = sigf(gf.y) * c2[ci].y + sigf(gi.y) * tanh_(gg.y);
            c2[ci] = make_float2(cnx, cny);
            float2 hn = make_float2(sigf(go.x) * tanh_(cnx), sigf(go.y) * tanh_(cny));
            hout[(c0 + ci) * NPAIR + tid] = hn;
        }
    }

    // ---------------- decoder: 256 steps ----------------
    float2 x2;
    x2.x = __ldg(inp + b0 * SEQ + (SEQ - 1));
    x2.y = __ldg(inp + b1 * SEQ + (SEQ - 1));

    for (int d = 0; d < TGT; d++) {
        int s = SEQ + d;
        bt += NCTA;
        grid_barrier(bt);

        float2 acc[16];
#pragma unroll
        for (int g = 0; g < 16; g++) {
            float b = bsD[g];
            acc[g] = make_float2(b, b);
        }
        // xd accumulates dot(h_{t-1}, lin_W) == previous step's output (the fed-back x)
        float2 xd = make_float2(0.f, 0.f);
        kloop<true>(g_h[s & 1], wsD, ls, tid, acc, xd);

        if (d > 0) {
            x2.x = xd.x + s_linb;
            x2.y = xd.y + s_linb;
            if (cta == 0) {   // every CTA computes it identically; CTA 0 emits
                out[b0 * TGT + (d - 1)] = x2.x;
                out[b1 * TGT + (d - 1)] = x2.y;
            }
        }
        // add the x * Wih contribution (x only known after the h reduction)
#pragma unroll
        for (int g = 0; g < 16; g++) {
            float w = wxD[g];
            acc[g].x = fmaf(x2.x, w, acc[g].x);
            acc[g].y = fmaf(x2.y, w, acc[g].y);
        }

        float2* hout = g_h[(s + 1) & 1];
#pragma unroll
        for (int ci = 0; ci < 4; ci++) {
            float2 gi = acc[ci], gf = acc[4 + ci], gg = acc[8 + ci], go = acc[12 + ci];
            float cnx = sigf(gf.x) * c2[ci].x + sigf(gi.x) * tanh_(gg.x);
            float cny = sigf(gf.y) * c2[ci].y + sigf(gi.y) * tanh_(gg.y);
            c2[ci] = make_float2(cnx, cny);
            float2 hn = make_float2(sigf(go.x) * tanh_(cnx), sigf(go.y) * tanh_(cny));
            hout[(c0 + ci) * NPAIR + tid] = hn;
        }
    }

    // ---------------- final output (dot of last decoder h) ----------------
    bt += NCTA;
    grid_barrier(bt);
    if (cta == 0) {
        const float2* hin = g_h[(SEQ + TGT) & 1];
        float2 xd = make_float2(0.f, 0.f);
        for (int k = 0; k < HID; k++) {
            float2 hk = __ldcg(hin + k * NPAIR + tid);
            ffma2(xd, hk, ls[k], xd);
        }
        out[b0 * TGT + (TGT - 1)] = xd.x + s_linb;
        out[b1 * TGT + (TGT - 1)] = xd.y + s_linb;
    }
}

extern "C" void kernel_launch(void* const* d_in, const int* in_sizes, int n_in,
                              void* d_out, int out_size) {
    const float* inp  = (const float*)d_in[0];
    const float* eWih = (const float*)d_in[1];
    const float* eWhh = (const float*)d_in[2];
    const float* ebih = (const float*)d_in[3];
    const float* ebhh = (const float*)d_in[4];
    const float* dWih = (const float*)d_in[5];
    const float* dWhh = (const float*)d_in[6];
    const float* dbih = (const float*)d_in[7];
    const float* dbhh = (const float*)d_in[8];
    const float* linW = (const float*)d_in[9];
    const float* linb = (const float*)d_in[10];
    float* out = (float*)d_out;

    size_t smem = (size_t)(2 * 16 * HID + HID) * sizeof(float2);  // 132 KB
    cudaFuncSetAttribute((const void*)seq2seq_kernel,
                         cudaFuncAttributeMaxDynamicSharedMemorySize, (int)smem);

    k_init<<<1, 1>>>();
    seq2seq_kernel<<<NCTA, TPB, smem>>>(inp, eWih, eWhh, ebih, ebhh,
                                        dWih, dWhh, dbih, dbhh, linW, linb, out);
}

// round 5
// speedup vs baseline: 1.0786x; 1.0786x over previous
#include <cuda_runtime.h>
#include <cstdint>

#define BSZ   256
#define SEQ   1024
#define HID   512
#define TGT   256
#define NCTA  128
#define TPB   256
#define KP    (HID / 2)   // k-pairs

typedef unsigned long long ull;

// Hidden state, double buffered, layout [k_pair][batch] as packed float2 (b64).
__device__ ull g_h[2][KP * BSZ];
__device__ unsigned g_bar;

__global__ void k_init() { g_bar = 0u; }

// Native b64 packed dual-FMA — no MOV packing, operands live in register pairs.
__device__ __forceinline__ ull ffma2(ull a, ull b, ull c) {
    ull d;
    asm("fma.rn.f32x2 %0, %1, %2, %3;" : "=l"(d) : "l"(a), "l"(b), "l"(c));
    return d;
}

__device__ __forceinline__ ull pack2(float x, float y) {
    float2 t = make_float2(x, y);
    return *reinterpret_cast<ull*>(&t);
}
__device__ __forceinline__ float lanesum(ull v) {
    float2 t = *reinterpret_cast<float2*>(&v);
    return t.x + t.y;
}

__device__ __forceinline__ float sigf(float x) {
    return __fdividef(1.0f, 1.0f + __expf(-x));
}
__device__ __forceinline__ float tanh_(float x) {
    return __fdividef(2.0f, 1.0f + __expf(-2.0f * x)) - 1.0f;
}

// Monotonic-counter grid barrier (128 CTAs co-resident, 1/SM)
__device__ __forceinline__ void grid_barrier(unsigned target) {
    __syncthreads();
    if (threadIdx.x == 0) {
        __threadfence();
        atomicAdd(&g_bar, 1u);
        unsigned v;
        do {
            asm volatile("ld.acquire.gpu.u32 %0, [%1];" : "=r"(v) : "l"(&g_bar));
        } while (v < target);
    }
    __syncthreads();
}

// Two k-pairs (4 k values): h0 covers ks {2kp, 2kp+1}, h1 {2kp+2, 2kp+3}
template <bool XDOT>
__device__ __forceinline__ void compute2(ull h0, ull h1,
                                         const float* __restrict__ ws,
                                         const float* __restrict__ ls,
                                         int kp, ull* acc, ull& xd) {
    if (XDOT) {
        ulonglong2 lw = *reinterpret_cast<const ulonglong2*>(ls + 2 * kp);
        xd = ffma2(h0, lw.x, xd);
        xd = ffma2(h1, lw.y, xd);
    }
#pragma unroll
    for (int g = 0; g < 16; g++) {
        ulonglong2 w = *reinterpret_cast<const ulonglong2*>(ws + g * HID + 2 * kp);
        acc[g] = ffma2(h0, w.x, acc[g]);
        acc[g] = ffma2(h1, w.y, acc[g]);
    }
}

// Full K=512 reduction; hin pre-offset by batch row (stride BSZ per k-pair)
template <bool XDOT>
__device__ __forceinline__ void kloop(const ull* __restrict__ hin,
                                      const float* __restrict__ ws,
                                      const float* __restrict__ ls,
                                      ull* acc, ull& xd) {
    ull A0 = __ldcg(hin + 0 * BSZ), A1 = __ldcg(hin + 1 * BSZ);
    ull B0 = __ldcg(hin + 2 * BSZ), B1 = __ldcg(hin + 3 * BSZ);

#pragma unroll 1
    for (int kp = 0; kp < KP; kp += 4) {
        ull h0 = A0, h1 = A1;
        if (kp + 4 < KP) {
            A0 = __ldcg(hin + (kp + 4) * BSZ);
            A1 = __ldcg(hin + (kp + 5) * BSZ);
        }
        compute2<XDOT>(h0, h1, ws, ls, kp, acc, xd);

        ull h2 = B0, h3 = B1;
        if (kp + 4 < KP) {
            B0 = __ldcg(hin + (kp + 6) * BSZ);
            B1 = __ldcg(hin + (kp + 7) * BSZ);
        }
        compute2<XDOT>(h2, h3, ws, ls, kp + 2, acc, xd);
    }
}

extern __shared__ float dynsmem[];

__global__ void __launch_bounds__(TPB, 1)
seq2seq_kernel(const float* __restrict__ inp,
               const float* __restrict__ eWih, const float* __restrict__ eWhh,
               const float* __restrict__ ebih, const float* __restrict__ ebhh,
               const float* __restrict__ dWih, const float* __restrict__ dWhh,
               const float* __restrict__ dbih, const float* __restrict__ dbhh,
               const float* __restrict__ linW, const float* __restrict__ linb,
               float* __restrict__ out) {
    float* wsE = dynsmem;             // [16][HID] enc Whh slice (raw fp32)
    float* wsD = wsE + 16 * HID;      // [16][HID] dec Whh slice
    float* ls  = wsD + 16 * HID;      // [HID] lin_W
    __shared__ float bsE[16], wxE[16], bsD[16], wxD[16];
    __shared__ float s_linb;

    const int tid = threadIdx.x;
    const int b   = tid;              // one batch row per thread
    const int cta = blockIdx.x;
    const int c0  = cta * 4;          // first hidden column of this CTA
    const int kp0 = c0 >> 1;          // k-pair index of our output columns

    // Stage weights: gate-col g = gate*4 + ci -> row j = gate*HID + c0 + ci
    for (int idx = tid; idx < 16 * HID; idx += TPB) {
        int g = idx >> 9;
        int k = idx & (HID - 1);
        int gate = g >> 2, ci = g & 3;
        int j = gate * HID + c0 + ci;
        wsE[idx] = eWhh[j * HID + k];
        wsD[idx] = dWhh[j * HID + k];
    }
    for (int k = tid; k < HID; k += TPB) ls[k] = linW[k];
    if (tid < 16) {
        int gate = tid >> 2, ci = tid & 3;
        int j = gate * HID + c0 + ci;
        bsE[tid] = ebih[j] + ebhh[j];
        wxE[tid] = eWih[j];
        bsD[tid] = dbih[j] + dbhh[j];
        wxD[tid] = dWih[j];
    }
    if (tid == 0) s_linb = linb[0];

    // Zero this CTA's columns of h buffer 0
    g_h[0][(kp0 + 0) * BSZ + b] = 0ull;
    g_h[0][(kp0 + 1) * BSZ + b] = 0ull;

    float c4[4] = {0.f, 0.f, 0.f, 0.f};
    unsigned bt = 0;

    // ---------------- encoder: 1024 steps ----------------
    for (int s = 0; s < SEQ; s++) {
        bt += NCTA;
        grid_barrier(bt);

        float x = __ldg(inp + b * SEQ + s);

        ull acc[16];
#pragma unroll
        for (int g = 0; g < 16; g++)
            acc[g] = pack2(fmaf(x, wxE[g], bsE[g]), 0.f);

        ull xd = 0ull;
        kloop<false>(&g_h[s & 1][b], wsE, ls, acc, xd);

        ull* hout = &g_h[(s + 1) & 1][b];
        float hn[4];
#pragma unroll
        for (int ci = 0; ci < 4; ci++) {
            float gi = lanesum(acc[ci]);
            float gf = lanesum(acc[4 + ci]);
            float gg = lanesum(acc[8 + ci]);
            float go = lanesum(acc[12 + ci]);
            float cn = sigf(gf) * c4[ci] + sigf(gi) * tanh_(gg);
            c4[ci] = cn;
            hn[ci] = sigf(go) * tanh_(cn);
        }
        hout[(kp0 + 0) * BSZ] = pack2(hn[0], hn[1]);
        hout[(kp0 + 1) * BSZ] = pack2(hn[2], hn[3]);
    }

    // ---------------- decoder: 256 steps ----------------
    float x = __ldg(inp + b * SEQ + (SEQ - 1));

    for (int d = 0; d < TGT; d++) {
        int s = SEQ + d;
        bt += NCTA;
        grid_barrier(bt);

        ull acc[16];
#pragma unroll
        for (int g = 0; g < 16; g++)
            acc[g] = pack2(bsD[g], 0.f);

        // xd accumulates dot(h_{t-1}, lin_W) == previous step's output (fed-back x)
        ull xd = 0ull;
        kloop<true>(&g_h[s & 1][b], wsD, ls, acc, xd);

        if (d > 0) {
            x = lanesum(xd) + s_linb;
            if (cta == 0) out[b * TGT + (d - 1)] = x;
        }
        // add x * Wih contribution (x known only after the h reduction)
#pragma unroll
        for (int g = 0; g < 16; g++) {
            float2 u = *reinterpret_cast<float2*>(&acc[g]);
            u.x = fmaf(x, wxD[g], u.x);
            acc[g] = *reinterpret_cast<ull*>(&u);
        }

        ull* hout = &g_h[(s + 1) & 1][b];
        float hn[4];
#pragma unroll
        for (int ci = 0; ci < 4; ci++) {
            float gi = lanesum(acc[ci]);
            float gf = lanesum(acc[4 + ci]);
            float gg = lanesum(acc[8 + ci]);
            float go = lanesum(acc[12 + ci]);
            float cn = sigf(gf) * c4[ci] + sigf(gi) * tanh_(gg);
            c4[ci] = cn;
            hn[ci] = sigf(go) * tanh_(cn);
        }
        hout[(kp0 + 0) * BSZ] = pack2(hn[0], hn[1]);
        hout[(kp0 + 1) * BSZ] = pack2(hn[2], hn[3]);
    }

    // ---------------- final output (dot of last decoder h) ----------------
    bt += NCTA;
    grid_barrier(bt);
    if (cta == 0) {
        const ull* hin = &g_h[(SEQ + TGT) & 1][b];
        ull xd = 0ull;
        for (int kp = 0; kp < KP; kp++) {
            ull lw = *reinterpret_cast<const ull*>(ls + 2 * kp);
            xd = ffma2(__ldcg(hin + kp * BSZ), lw, xd);
        }
        out[b * TGT + (TGT - 1)] = lanesum(xd) + s_linb;
    }
}

extern "C" void kernel_launch(void* const* d_in, const int* in_sizes, int n_in,
                              void* d_out, int out_size) {
    const float* inp  = (const float*)d_in[0];
    const float* eWih = (const float*)d_in[1];
    const float* eWhh = (const float*)d_in[2];
    const float* ebih = (const float*)d_in[3];
    const float* ebhh = (const float*)d_in[4];
    const float* dWih = (const float*)d_in[5];
    const float* dWhh = (const float*)d_in[6];
    const float* dbih = (const float*)d_in[7];
    const float* dbhh = (const float*)d_in[8];
    const float* linW = (const float*)d_in[9];
    const float* linb = (const float*)d_in[10];
    float* out = (float*)d_out;

    size_t smem = (size_t)(2 * 16 * HID + HID) * sizeof(float);  // ~66 KB
    cudaFuncSetAttribute((const void*)seq2seq_kernel,
                         cudaFuncAttributeMaxDynamicSharedMemorySize, (int)smem);

    k_init<<<1, 1>>>();
    seq2seq_kernel<<<NCTA, TPB, smem>>>(inp, eWih, eWhh, ebih, ebhh,
                                        dWih, dWhh, dbih, dbhh, linW, linb, out);
}

// round 9
// speedup vs baseline: 1.1581x; 1.0737x over previous
#include <cuda_runtime.h>
#include <cstdint>

#define BSZ   256
#define SEQ   1024
#define HID   512
#define TGT   256
#define NCTA  128
#define TPB   512
#define KP    (HID / 2)    // total k-pairs
#define KP2   (KP / 2)     // k-pairs per K-half thread
#define REDW  17           // reduction slots per batch row (16 acc + xd)

typedef unsigned long long ull;

// Hidden state, double buffered, layout [k_pair][batch] as packed float2 (b64).
__device__ ull g_h[2][KP * BSZ];
__device__ unsigned g_bar;

__global__ void k_init() { g_bar = 0u; }

__device__ __forceinline__ ull ffma2(ull a, ull b, ull c) {
    ull d;
    asm("fma.rn.f32x2 %0, %1, %2, %3;" : "=l"(d) : "l"(a), "l"(b), "l"(c));
    return d;
}
__device__ __forceinline__ ull fadd2(ull a, ull b) {
    ull d;
    asm("add.rn.f32x2 %0, %1, %2;" : "=l"(d) : "l"(a), "l"(b));
    return d;
}

__device__ __forceinline__ ull pack2(float x, float y) {
    float2 t = make_float2(x, y);
    return *reinterpret_cast<ull*>(&t);
}
__device__ __forceinline__ float lanesum(ull v) {
    float2 t = *reinterpret_cast<float2*>(&v);
    return t.x + t.y;
}

__device__ __forceinline__ float sigf(float x) {
    return __fdividef(1.0f, 1.0f + __expf(-x));
}
__device__ __forceinline__ float tanh_(float x) {
    return __fdividef(2.0f, 1.0f + __expf(-2.0f * x)) - 1.0f;
}

// Monotonic-counter grid barrier (128 CTAs co-resident, 1/SM)
__device__ __forceinline__ void grid_barrier(unsigned target) {
    __syncthreads();
    if (threadIdx.x == 0) {
        __threadfence();
        atomicAdd(&g_bar, 1u);
        unsigned v;
        do {
            asm volatile("ld.acquire.gpu.u32 %0, [%1];" : "=r"(v) : "l"(&g_bar));
        } while (v < target);
    }
    __syncthreads();
}

// Two k-pairs (4 k values): h0 covers ks {2kp, 2kp+1}, h1 {2kp+2, 2kp+3}
template <bool XDOT>
__device__ __forceinline__ void compute2(ull h0, ull h1,
                                         const float* __restrict__ ws,
                                         const float* __restrict__ ls,
                                         int kp, ull* acc, ull& xd) {
    if (XDOT) {
        ulonglong2 lw = *reinterpret_cast<const ulonglong2*>(ls + 2 * kp);
        xd = ffma2(h0, lw.x, xd);
        xd = ffma2(h1, lw.y, xd);
    }
#pragma unroll
    for (int g = 0; g < 16; g++) {
        ulonglong2 w = *reinterpret_cast<const ulonglong2*>(ws + g * HID + 2 * kp);
        acc[g] = ffma2(h0, w.x, acc[g]);
        acc[g] = ffma2(h1, w.y, acc[g]);
    }
}

// K-half reduction (KP2 k-pairs); hin pre-offset to this thread's (khalf, b);
// ws/ls pre-offset by khalf*HID/2 floats so kp is local [0, KP2).
template <bool XDOT>
__device__ __forceinline__ void kloop(const ull* __restrict__ hin,
                                      const float* __restrict__ ws,
                                      const float* __restrict__ ls,
                                      ull* acc, ull& xd) {
    ull A0 = __ldcg(hin + 0 * BSZ), A1 = __ldcg(hin + 1 * BSZ);
    ull B0 = __ldcg(hin + 2 * BSZ), B1 = __ldcg(hin + 3 * BSZ);

#pragma unroll 1
    for (int kp = 0; kp < KP2; kp += 4) {
        ull h0 = A0, h1 = A1;
        if (kp + 4 < KP2) {
            A0 = __ldcg(hin + (kp + 4) * BSZ);
            A1 = __ldcg(hin + (kp + 5) * BSZ);
        }
        compute2<XDOT>(h0, h1, ws, ls, kp, acc, xd);

        ull h2 = B0, h3 = B1;
        if (kp + 4 < KP2) {
            B0 = __ldcg(hin + (kp + 6) * BSZ);
            B1 = __ldcg(hin + (kp + 7) * BSZ);
        }
        compute2<XDOT>(h2, h3, ws, ls, kp + 2, acc, xd);
    }
}

extern __shared__ float dynsmem[];

__global__ void __launch_bounds__(TPB, 1)
seq2seq_kernel(const float* __restrict__ inp,
               const float* __restrict__ eWih, const float* __restrict__ eWhh,
               const float* __restrict__ ebih, const float* __restrict__ ebhh,
               const float* __restrict__ dWih, const float* __restrict__ dWhh,
               const float* __restrict__ dbih, const float* __restrict__ dbhh,
               const float* __restrict__ linW, const float* __restrict__ linb,
               float* __restrict__ out) {
    float* wsE = dynsmem;             // [16][HID] enc Whh slice (raw fp32)
    float* wsD = wsE + 16 * HID;      // [16][HID] dec Whh slice
    float* ls  = wsD + 16 * HID;      // [HID] lin_W
    ull*   red = reinterpret_cast<ull*>(ls + HID);  // [BSZ][REDW] partial sums
    __shared__ float bsE[16], wxE[16], bsD[16], wxD[16];
    __shared__ float s_linb;

    const int tid = threadIdx.x;
    const int b   = tid & (BSZ - 1);  // batch row
    const int kh  = tid >> 8;         // K-half: 0 or 1
    const int cta = blockIdx.x;
    const int c0  = cta * 4;          // first hidden column of this CTA
    const int kp0 = c0 >> 1;          // k-pair index of our output columns

    // Stage weights: gate-col g = gate*4 + ci -> row j = gate*HID + c0 + ci
    for (int idx = tid; idx < 16 * HID; idx += TPB) {
        int g = idx >> 9;
        int k = idx & (HID - 1);
        int gate = g >> 2, ci = g & 3;
        int j = gate * HID + c0 + ci;
        wsE[idx] = eWhh[j * HID + k];
        wsD[idx] = dWhh[j * HID + k];
    }
    for (int k = tid; k < HID; k += TPB) ls[k] = linW[k];
    if (tid < 16) {
        int gate = tid >> 2, ci = tid & 3;
        int j = gate * HID + c0 + ci;
        bsE[tid] = ebih[j] + ebhh[j];
        wxE[tid] = eWih[j];
        bsD[tid] = dbih[j] + dbhh[j];
        wxD[tid] = dWih[j];
    }
    if (tid == 0) s_linb = linb[0];

    // Zero this CTA's columns of h buffer 0 (half-0 threads own the writes)
    if (kh == 0) {
        g_h[0][(kp0 + 0) * BSZ + b] = 0ull;
        g_h[0][(kp0 + 1) * BSZ + b] = 0ull;
    }

    float c4[4] = {0.f, 0.f, 0.f, 0.f};
    unsigned bt = 0;

    // This thread's pre-offset views for its K-half
    const int hoff = kh * KP2 * BSZ + b;
    const float* wsEh = wsE + kh * (HID / 2);
    const float* wsDh = wsD + kh * (HID / 2);
    const float* lsh  = ls  + kh * (HID / 2);
    ull* myred = red + b * REDW;

    // ---------------- encoder: 1024 steps ----------------
    for (int s = 0; s < SEQ; s++) {
        bt += NCTA;
        grid_barrier(bt);

        ull acc[16];
        if (kh == 0) {
            float x = __ldg(inp + b * SEQ + s);
#pragma unroll
            for (int g = 0; g < 16; g++)
                acc[g] = pack2(fmaf(x, wxE[g], bsE[g]), 0.f);
        } else {
#pragma unroll
            for (int g = 0; g < 16; g++) acc[g] = 0ull;
        }

        ull xd = 0ull;
        kloop<false>(&g_h[s & 1][hoff], wsEh, lsh, acc, xd);

        if (kh == 1) {
#pragma unroll
            for (int g = 0; g < 16; g++) myred[g] = acc[g];
        }
        __syncthreads();

        if (kh == 0) {
#pragma unroll
            for (int g = 0; g < 16; g++) acc[g] = fadd2(acc[g], myred[g]);

            ull* hout = &g_h[(s + 1) & 1][b];
            float hn[4];
#pragma unroll
            for (int ci = 0; ci < 4; ci++) {
                float gi = lanesum(acc[ci]);
                float gf = lanesum(acc[4 + ci]);
                float gg = lanesum(acc[8 + ci]);
                float go = lanesum(acc[12 + ci]);
                float cn = sigf(gf) * c4[ci] + sigf(gi) * tanh_(gg);
                c4[ci] = cn;
                hn[ci] = sigf(go) * tanh_(cn);
            }
            hout[(kp0 + 0) * BSZ] = pack2(hn[0], hn[1]);
            hout[(kp0 + 1) * BSZ] = pack2(hn[2], hn[3]);
        }
    }

    // ---------------- decoder: 256 steps ----------------
    float x = __ldg(inp + b * SEQ + (SEQ - 1));   // x_0 (only half-0 uses it)

    for (int d = 0; d < TGT; d++) {
        int s = SEQ + d;
        bt += NCTA;
        grid_barrier(bt);

        ull acc[16];
        if (kh == 0) {
#pragma unroll
            for (int g = 0; g < 16; g++) acc[g] = pack2(bsD[g], 0.f);
        } else {
#pragma unroll
            for (int g = 0; g < 16; g++) acc[g] = 0ull;
        }

        // xd accumulates dot(h_{t-1}, lin_W) over this K-half
        ull xd = 0ull;
        kloop<true>(&g_h[s & 1][hoff], wsDh, lsh, acc, xd);

        if (kh == 1) {
#pragma unroll
            for (int g = 0; g < 16; g++) myred[g] = acc[g];
            myred[16] = xd;
        }
        __syncthreads();

        if (kh == 0) {
#pragma unroll
            for (int g = 0; g < 16; g++) acc[g] = fadd2(acc[g], myred[g]);
            xd = fadd2(xd, myred[16]);

            if (d > 0) {
                x = lanesum(xd) + s_linb;    // out_{d-1} == fed-back x_d
                if (cta == 0) out[b * TGT + (d - 1)] = x;
            }
            // add x * Wih contribution (lane 0 only)
#pragma unroll
            for (int g = 0; g < 16; g++) {
                float2 u = *reinterpret_cast<float2*>(&acc[g]);
                u.x = fmaf(x, wxD[g], u.x);
                acc[g] = *reinterpret_cast<ull*>(&u);
            }

            ull* hout = &g_h[(s + 1) & 1][b];
            float hn[4];
#pragma unroll
            for (int ci = 0; ci < 4; ci++) {
                float gi = lanesum(acc[ci]);
                float gf = lanesum(acc[4 + ci]);
                float gg = lanesum(acc[8 + ci]);
                float go = lanesum(acc[12 + ci]);
                float cn = sigf(gf) * c4[ci] + sigf(gi) * tanh_(gg);
                c4[ci] = cn;
                hn[ci] = sigf(go) * tanh_(cn);
            }
            hout[(kp0 + 0) * BSZ] = pack2(hn[0], hn[1]);
            hout[(kp0 + 1) * BSZ] = pack2(hn[2], hn[3]);
        }
    }

    // ---------------- final output (dot of last decoder h) ----------------
    bt += NCTA;
    grid_barrier(bt);
    if (cta == 0 && kh == 0) {
        const ull* hin = &g_h[(SEQ + TGT) & 1][b];
        ull xd = 0ull;
        for (int kp = 0; kp < KP; kp++) {
            ull lw = *reinterpret_cast<const ull*>(ls + 2 * kp);
            xd = ffma2(__ldcg(hin + kp * BSZ), lw, xd);
        }
        out[b * TGT + (TGT - 1)] = lanesum(xd) + s_linb;
    }
}

extern "C" void kernel_launch(void* const* d_in, const int* in_sizes, int n_in,
                              void* d_out, int out_size) {
    const float* inp  = (const float*)d_in[0];
    const float* eWih = (const float*)d_in[1];
    const float* eWhh = (const float*)d_in[2];
    const float* ebih = (const float*)d_in[3];
    const float* ebhh = (const float*)d_in[4];
    const float* dWih = (const float*)d_in[5];
    const float* dWhh = (const float*)d_in[6];
    const float* dbih = (const float*)d_in[7];
    const float* dbhh = (const float*)d_in[8];
    const float* linW = (const float*)d_in[9];
    const float* linb = (const float*)d_in[10];
    float* out = (float*)d_out;

    // 66 KB weights + 34 KB reduction buffer
    size_t smem = (size_t)(2 * 16 * HID + HID) * sizeof(float)
                + (size_t)BSZ * REDW * sizeof(ull);
    cudaFuncSetAttribute((const void*)seq2seq_kernel,
                         cudaFuncAttributeMaxDynamicSharedMemorySize, (int)smem);

    k_init<<<1, 1>>>();
    seq2seq_kernel<<<NCTA, TPB, smem>>>(inp, eWih, eWhh, ebih, ebhh,
                                        dWih, dWhh, dbih, dbhh, linW, linb, out);
}